// round 8
// baseline (speedup 1.0000x reference)
#include <cuda_runtime.h>

// SSIM (skimage-style, win=7, data_range=2) of two 4096x4096 f32 images.
// Valid region 4090x4090, scalar mean output.

#define IMW 4096
#define IMH 4096
#define OWD 4090          // valid output width  (W - 6)
#define OHT 4090          // valid output height (H - 6)
#define CT  158           // column tiles: ceil(4090 / 26)
#define RH  128           // output rows per strip
#define RSTRIPS 32        // ceil(4090 / 128)
#define WPB 8             // warps per block
#define NBLK (CT * RSTRIPS / WPB)   // 632

__device__ double g_ssim_sum;

__global__ void ssim_zero() { g_ssim_sum = 0.0; }

// Sum of v over lanes [t, t+6]. Valid for t <= 25.
__device__ __forceinline__ float hsum7(float v) {
    const unsigned m = 0xffffffffu;
    float s2 = v + __shfl_down_sync(m, v, 1);   // v[t] + v[t+1]
    float s4 = s2 + __shfl_down_sync(m, s2, 2); // v[t..t+3]
    float r  = s4 + __shfl_down_sync(m, s2, 4); // + v[t+4..t+5]
    return r + __shfl_down_sync(m, v, 6);       // + v[t+6]
}

__global__ __launch_bounds__(WPB * 32) void ssim_main(
    const float* __restrict__ O, const float* __restrict__ T)
{
    const int lane  = threadIdx.x & 31;
    const int warp  = threadIdx.x >> 5;
    const int gw    = blockIdx.x * WPB + warp;
    const int tile  = gw % CT;
    const int strip = gw / CT;

    const int colv = tile * 26 + lane;                 // input column this lane loads
    const int cin  = colv < IMW ? colv : (IMW - 1);    // clamp (clamped lanes are masked)
    const bool colvalid = (lane < 26) && (colv < OWD); // lane produces a valid output col

    const int r0       = strip * RH;
    const int rows_out = min(RH, OHT - r0);

    // Scaled constants: working with raw 7x7 window sums S* (= 49*mean).
    // All 1/49^2 normalizations cancel in (A1*A2)/(B1*B2).
    const float C1p = 0.9604f;                 // C1 * 49^2,  C1 = (0.01*2)^2
    const float C2p = 8.6436f;                 // C2 * 49^2,  C2 = (0.03*2)^2
    const float a2s = 98.0f * (49.0f / 48.0f); // 2*COV*49
    const float a2p = 2.0f  * (49.0f / 48.0f); // 2*COV
    const float b2s = 49.0f * (49.0f / 48.0f); // COV*49
    const float b2q = (49.0f / 48.0f);         // COV

    // Vertical 7-row sliding window state (per column/lane).
    float ro[7], rt[7];
    float so = 0.f, st = 0.f, soo = 0.f, stt = 0.f, sot = 0.f;

    int idx = r0 * IMW + cin;
    #pragma unroll
    for (int k = 0; k < 6; k++) {              // prime with rows r0 .. r0+5
        float o = __ldg(O + idx);
        float t = __ldg(T + idx);
        idx += IMW;
        ro[k] = o; rt[k] = t;
        so += o; st += t;
        soo = fmaf(o, o, soo);
        stt = fmaf(t, t, stt);
        sot = fmaf(o, t, sot);
    }
    ro[6] = 0.f; rt[6] = 0.f;

    float acc = 0.f;

    // Body for output row j (j % 7 == K, compile-time ring slots).
    #define SSIM_BODY(K) do { \
        float o = __ldg(O + idx); \
        float t = __ldg(T + idx); \
        idx += IMW; \
        so += o; st += t; \
        soo = fmaf(o, o, soo); \
        stt = fmaf(t, t, stt); \
        sot = fmaf(o, t, sot); \
        ro[((K) + 6) % 7] = o; rt[((K) + 6) % 7] = t; \
        float Sx  = hsum7(so),  Sy  = hsum7(st); \
        float Sxx = hsum7(soo), Syy = hsum7(stt), Sxy = hsum7(sot); \
        float P  = Sx * Sy; \
        float Qx = Sx * Sx, Qy = Sy * Sy; \
        float A1 = fmaf(2.f, P, C1p); \
        float B1 = Qx + Qy + C1p; \
        float A2 = fmaf(a2s, Sxy, fmaf(-a2p, P, C2p)); \
        float B2 = fmaf(b2s, Sxx + Syy, fmaf(-b2q, Qx + Qy, C2p)); \
        float Sval = __fdividef(A1 * A2, B1 * B2); \
        if (colvalid) acc += Sval; \
        float oo = ro[(K)], to = rt[(K)]; \
        so -= oo; st -= to; \
        soo = fmaf(-oo, oo, soo); \
        stt = fmaf(-to, to, stt); \
        sot = fmaf(-oo, to, sot); \
    } while (0)

    const int full = (rows_out / 7) * 7;
    int j = 0;
    while (j < full) {
        #pragma unroll
        for (int k = 0; k < 7; k++) { SSIM_BODY(k); }
        j += 7;
    }
    // Remainder (< 7 rows); j == full ≡ 0 (mod 7) so ring slots still line up.
    #pragma unroll
    for (int k = 0; k < 7; k++) {
        if (j + k < rows_out) { SSIM_BODY(k); }
    }
    #undef SSIM_BODY

    // Warp reduce.
    #pragma unroll
    for (int off = 16; off; off >>= 1)
        acc += __shfl_xor_sync(0xffffffffu, acc, off);

    __shared__ float wsum[WPB];
    if (lane == 0) wsum[warp] = acc;
    __syncthreads();
    if (threadIdx.x == 0) {
        float b = 0.f;
        #pragma unroll
        for (int i = 0; i < WPB; i++) b += wsum[i];
        atomicAdd(&g_ssim_sum, (double)b);
    }
}

__global__ void ssim_fin(float* out) {
    out[0] = (float)(g_ssim_sum * (1.0 / ((double)OWD * (double)OHT)));
}

extern "C" void kernel_launch(void* const* d_in, const int* in_sizes, int n_in,
                              void* d_out, int out_size) {
    const float* O = (const float*)d_in[0];
    const float* T = (const float*)d_in[1];
    ssim_zero<<<1, 1>>>();
    ssim_main<<<NBLK, WPB * 32>>>(O, T);
    ssim_fin<<<1, 1>>>((float*)d_out);
}

// round 9
// speedup vs baseline: 1.7717x; 1.7717x over previous
#include <cuda_runtime.h>

// SSIM (skimage, win=7, data_range=2) of two 4096x4096 f32 images -> scalar mean.
// Register-resident separable 7x7 box sums: horizontal 7-sums per row in
// registers (thread owns 2 output columns), vertical 7-window via incremental
// sliding sum with a mod-7 register ring. No shuffles / no smem in hot loop.

#define IMW 4096
#define OWD 4090
#define OHT 4090
#define RH  64
#define CB  8            // column blocks (8*256 = 2048 column-pairs >= 2045)
#define TPB 256
#define NSTRIPS 64       // ceil(4090/64)

__device__ double g_ssim_sum;

__global__ void ssim_zero() { g_ssim_sum = 0.0; }

__global__ __launch_bounds__(TPB, 2) void ssim_main(
    const float* __restrict__ O, const float* __restrict__ T)
{
    const int pairIdx = blockIdx.x * TPB + threadIdx.x;   // 0..2047
    int c = pairIdx * 2;                                  // first output col of pair
    const bool valid = (c < OWD);     // c<=4088 -> cols c and c+1 both valid
    if (c > IMW - 8) c = IMW - 8;     // clamp loads into [0,4095]; acc masked later

    const int rbase    = blockIdx.y * RH;
    const int rows_out = min(RH, OHT - rbase);

    const float2* __restrict__ Of2 = (const float2*)O;
    const float2* __restrict__ Tf2 = (const float2*)T;
    int p = rbase * (IMW / 2) + (c >> 1);

    // Scaled constants (raw 7x7 sums S = 49*mean; 1/49^2 cancels in the ratio).
    const float C1p = 0.9604f;                 // C1 * 49^2
    const float C2p = 8.6436f;                 // C2 * 49^2
    const float a2s = 98.0f * (49.0f / 48.0f); // 2*COV*49
    const float a2p = 2.0f  * (49.0f / 48.0f); // 2*COV
    const float b2s = 49.0f * (49.0f / 48.0f); // COV*49
    const float b2q = (49.0f / 48.0f);         // COV

    // Ring buffers of per-row horizontal 7-sums: 4 quantities x 2 cols x 7 rows.
    float RO0[7], RO1[7], RT0[7], RT1[7], RQ0[7], RQ1[7], RR0[7], RR1[7];
    // Vertical running sums (over 7 rows of horizontal sums).
    float Vo0 = 0.f, Vo1 = 0.f, Vt0 = 0.f, Vt1 = 0.f;
    float Vq0 = 0.f, Vq1 = 0.f, Vr0 = 0.f, Vr1 = 0.f;

    float acc = 0.f;

// Load one input row (8 px per image), produce horizontal 7-sums for the
// thread's two output columns, for the 4 quantities (o, t, o^2+t^2, o*t).
#define ROWH(HO0,HO1,HT0,HT1,HQ0,HQ1,HR0,HR1) \
    float HO0,HO1,HT0,HT1,HQ0,HQ1,HR0,HR1; \
    { \
        float2 a0 = Of2[p], a1 = Of2[p+1], a2 = Of2[p+2], a3 = Of2[p+3]; \
        float2 b0 = Tf2[p], b1 = Tf2[p+1], b2 = Tf2[p+2], b3 = Tf2[p+3]; \
        p += IMW / 2; \
        float o0=a0.x,o1=a0.y,o2=a1.x,o3=a1.y,o4=a2.x,o5=a2.y,o6=a3.x,o7=a3.y; \
        float t0=b0.x,t1=b0.y,t2=b1.x,t3=b1.y,t4=b2.x,t5=b2.y,t6=b3.x,t7=b3.y; \
        HO0 = ((o0+o1)+(o2+o3))+((o4+o5)+o6);  HO1 = (HO0 - o0) + o7; \
        HT0 = ((t0+t1)+(t2+t3))+((t4+t5)+t6);  HT1 = (HT0 - t0) + t7; \
        float q0=fmaf(o0,o0,t0*t0), q1=fmaf(o1,o1,t1*t1); \
        float q2=fmaf(o2,o2,t2*t2), q3=fmaf(o3,o3,t3*t3); \
        float q4=fmaf(o4,o4,t4*t4), q5=fmaf(o5,o5,t5*t5); \
        float q6=fmaf(o6,o6,t6*t6), q7=fmaf(o7,o7,t7*t7); \
        HQ0 = ((q0+q1)+(q2+q3))+((q4+q5)+q6);  HQ1 = (HQ0 - q0) + q7; \
        float w0=o0*t0, w1=o1*t1, w2=o2*t2, w3=o3*t3; \
        float w4=o4*t4, w5=o5*t5, w6=o6*t6, w7=o7*t7; \
        HR0 = ((w0+w1)+(w2+w3))+((w4+w5)+w6);  HR1 = (HR0 - w0) + w7; \
    }

#define SSIM1(Sx,Sy,Sqq,Sxy) do { \
        float P  = (Sx) * (Sy); \
        float QQ = fmaf((Sx), (Sx), (Sy) * (Sy)); \
        float A1 = fmaf(2.f, P, C1p); \
        float B1 = QQ + C1p; \
        float A2 = fmaf(a2s, (Sxy), fmaf(-a2p, P,  C2p)); \
        float B2 = fmaf(b2s, (Sqq), fmaf(-b2q, QQ, C2p)); \
        acc += __fdividef(A1 * A2, B1 * B2); \
    } while (0)

    // Prime with input rows rbase .. rbase+5 (ring slots 0..5).
    #pragma unroll
    for (int k = 0; k < 6; k++) {
        ROWH(ho0,ho1,ht0,ht1,hq0,hq1,hr0,hr1);
        Vo0 += ho0; Vo1 += ho1; Vt0 += ht0; Vt1 += ht1;
        Vq0 += hq0; Vq1 += hq1; Vr0 += hr0; Vr1 += hr1;
        RO0[k]=ho0; RO1[k]=ho1; RT0[k]=ht0; RT1[k]=ht1;
        RQ0[k]=hq0; RQ1[k]=hq1; RR0[k]=hr0; RR1[k]=hr1;
    }
    RO0[6]=0.f; RO1[6]=0.f; RT0[6]=0.f; RT1[6]=0.f;
    RQ0[6]=0.f; RQ1[6]=0.f; RR0[6]=0.f; RR1[6]=0.f;

// Output row j (K = j % 7): add new row's h, compute SSIM, drop oldest row.
#define BODY(K) do { \
        ROWH(ho0,ho1,ht0,ht1,hq0,hq1,hr0,hr1); \
        Vo0 += ho0; Vo1 += ho1; Vt0 += ht0; Vt1 += ht1; \
        Vq0 += hq0; Vq1 += hq1; Vr0 += hr0; Vr1 += hr1; \
        SSIM1(Vo0, Vt0, Vq0, Vr0); \
        SSIM1(Vo1, Vt1, Vq1, Vr1); \
        Vo0 -= RO0[K]; Vo1 -= RO1[K]; Vt0 -= RT0[K]; Vt1 -= RT1[K]; \
        Vq0 -= RQ0[K]; Vq1 -= RQ1[K]; Vr0 -= RR0[K]; Vr1 -= RR1[K]; \
        RO0[((K)+6)%7]=ho0; RO1[((K)+6)%7]=ho1; \
        RT0[((K)+6)%7]=ht0; RT1[((K)+6)%7]=ht1; \
        RQ0[((K)+6)%7]=hq0; RQ1[((K)+6)%7]=hq1; \
        RR0[((K)+6)%7]=hr0; RR1[((K)+6)%7]=hr1; \
    } while (0)

    const int full = (rows_out / 7) * 7;
    int j = 0;
    while (j < full) {
        BODY(0); BODY(1); BODY(2); BODY(3); BODY(4); BODY(5); BODY(6);
        j += 7;
    }
    const int rem = rows_out - full;   // 0..6
    if (rem > 0) BODY(0);
    if (rem > 1) BODY(1);
    if (rem > 2) BODY(2);
    if (rem > 3) BODY(3);
    if (rem > 4) BODY(4);
    if (rem > 5) BODY(5);

#undef BODY
#undef SSIM1
#undef ROWH

    // Mask clamped duplicate threads, then reduce.
    if (!valid) acc = 0.f;

    #pragma unroll
    for (int off = 16; off; off >>= 1)
        acc += __shfl_xor_sync(0xffffffffu, acc, off);

    __shared__ float wsum[TPB / 32];
    const int lane = threadIdx.x & 31;
    const int warp = threadIdx.x >> 5;
    if (lane == 0) wsum[warp] = acc;
    __syncthreads();
    if (threadIdx.x == 0) {
        float b = 0.f;
        #pragma unroll
        for (int i = 0; i < TPB / 32; i++) b += wsum[i];
        atomicAdd(&g_ssim_sum, (double)b);
    }
}

__global__ void ssim_fin(float* out) {
    out[0] = (float)(g_ssim_sum * (1.0 / ((double)OWD * (double)OHT)));
}

extern "C" void kernel_launch(void* const* d_in, const int* in_sizes, int n_in,
                              void* d_out, int out_size) {
    const float* O = (const float*)d_in[0];
    const float* T = (const float*)d_in[1];
    ssim_zero<<<1, 1>>>();
    ssim_main<<<dim3(CB, NSTRIPS), TPB>>>(O, T);
    ssim_fin<<<1, 1>>>((float*)d_out);
}

// round 12
// speedup vs baseline: 1.8381x; 1.0375x over previous
#include <cuda_runtime.h>

// SSIM (skimage, win=7, data_range=2) of two 4096x4096 f32 -> scalar mean.
// Single kernel: 4 output cols/thread, register-resident separable 7x7 sums,
// last-block finalization (no zero/fin launches).

#define IMW  4096
#define OWD  4090
#define OHT  4090
#define TPB  128
#define GX   8            // 8 blocks * 128 thr * 4 cols = 4096 columns
#define RH   112          // output rows per strip (multiple of 7)
#define NSTR 37           // ceil(4090/112)
#define NBLK (GX * NSTR)  // 296 = 148 * 2 -> one balanced wave at 2 CTA/SM

__device__ double   g_sum;   // zero-initialized; reset by last block each run
__device__ unsigned g_cnt;

__global__ __launch_bounds__(TPB, 2) void ssim_main(
    const float* __restrict__ O, const float* __restrict__ T,
    float* __restrict__ out)
{
    const int gid  = blockIdx.x * TPB + threadIdx.x;   // 0..1023
    const int ocol = gid * 4;                          // first output col
    int  c   = ocol;
    bool ld3 = (c + 11 < IMW);                // third float4 in-bounds?
    if (c >= OWD) { c = 4080; ld3 = true; }   // fully-masked thread: safe loads

    const int r0       = blockIdx.y * RH;
    const int rows_out = min(RH, OHT - r0);

    const float4* __restrict__ O4 = (const float4*)O;
    const float4* __restrict__ T4 = (const float4*)T;
    int p = r0 * (IMW / 4) + (c >> 2);

    // Scaled constants: raw 7x7 sums S = 49*mean; 1/49^2 cancels in the ratio.
    const float C1p = 0.9604f;                 // C1 * 49^2
    const float C2p = 8.6436f;                 // C2 * 49^2
    const float a2s = 98.0f * (49.0f / 48.0f); // 2*COV*49
    const float a2p = 2.0f  * (49.0f / 48.0f); // 2*COV
    const float b2s = 49.0f * (49.0f / 48.0f); // COV*49
    const float b2q = (49.0f / 48.0f);         // COV

    // Rings of per-row horizontal 7-sums: quantities {o, t, o^2+t^2, o*t} x 4 cols.
    float rO0[7], rO1[7], rO2[7], rO3[7];
    float rT0[7], rT1[7], rT2[7], rT3[7];
    float rQ0[7], rQ1[7], rQ2[7], rQ3[7];
    float rR0[7], rR1[7], rR2[7], rR3[7];
    // Vertical running 7-row sums.
    float vO0=0.f,vO1=0.f,vO2=0.f,vO3=0.f, vT0=0.f,vT1=0.f,vT2=0.f,vT3=0.f;
    float vQ0=0.f,vQ1=0.f,vQ2=0.f,vQ3=0.f, vR0=0.f,vR1=0.f,vR2=0.f,vR3=0.f;
    float a0=0.f, a1=0.f, a2c=0.f, a3=0.f;

// Load 12 px/row/image, make horizontal 7-sums for 4 output cols, 4 quantities.
#define ROWH() \
    float hO0,hO1,hO2,hO3, hT0,hT1,hT2,hT3, hQ0,hQ1,hQ2,hQ3, hR0,hR1,hR2,hR3; \
    { \
        float4 A0 = O4[p], A1 = O4[p+1], B0 = T4[p], B1 = T4[p+1]; \
        float4 A2 = make_float4(0.f,0.f,0.f,0.f), B2 = A2; \
        if (ld3) { A2 = O4[p+2]; B2 = T4[p+2]; } \
        p += IMW / 4; \
        float o0=A0.x,o1=A0.y,o2=A0.z,o3=A0.w,o4=A1.x,o5=A1.y,o6=A1.z,o7=A1.w,o8=A2.x,o9=A2.y; \
        float t0=B0.x,t1=B0.y,t2=B0.z,t3=B0.w,t4=B1.x,t5=B1.y,t6=B1.z,t7=B1.w,t8=B2.x,t9=B2.y; \
        hO0 = ((o0+o1)+(o2+o3))+((o4+o5)+o6); \
        hO1 = (hO0-o0)+o7; hO2 = (hO1-o1)+o8; hO3 = (hO2-o2)+o9; \
        hT0 = ((t0+t1)+(t2+t3))+((t4+t5)+t6); \
        hT1 = (hT0-t0)+t7; hT2 = (hT1-t1)+t8; hT3 = (hT2-t2)+t9; \
        float q0=fmaf(o0,o0,t0*t0), q1=fmaf(o1,o1,t1*t1), q2=fmaf(o2,o2,t2*t2); \
        float q3=fmaf(o3,o3,t3*t3), q4=fmaf(o4,o4,t4*t4), q5=fmaf(o5,o5,t5*t5); \
        float q6=fmaf(o6,o6,t6*t6), q7=fmaf(o7,o7,t7*t7), q8=fmaf(o8,o8,t8*t8); \
        float q9=fmaf(o9,o9,t9*t9); \
        hQ0 = ((q0+q1)+(q2+q3))+((q4+q5)+q6); \
        hQ1 = (hQ0-q0)+q7; hQ2 = (hQ1-q1)+q8; hQ3 = (hQ2-q2)+q9; \
        float w0=o0*t0, w1=o1*t1, w2=o2*t2, w3=o3*t3, w4=o4*t4; \
        float w5=o5*t5, w6=o6*t6, w7=o7*t7, w8=o8*t8, w9=o9*t9; \
        hR0 = ((w0+w1)+(w2+w3))+((w4+w5)+w6); \
        hR1 = (hR0-w0)+w7; hR2 = (hR1-w1)+w8; hR3 = (hR2-w2)+w9; \
    }

#define SSIM1(Sx,Sy,Sqq,Sxy,ACC) do { \
        float P  = (Sx) * (Sy); \
        float QQ = fmaf((Sx), (Sx), (Sy) * (Sy)); \
        float A1v = fmaf(2.f, P, C1p); \
        float B1v = QQ + C1p; \
        float A2v = fmaf(a2s, (Sxy), fmaf(-a2p, P,  C2p)); \
        float B2v = fmaf(b2s, (Sqq), fmaf(-b2q, QQ, C2p)); \
        ACC += __fdividef(A1v * A2v, B1v * B2v); \
    } while (0)

#define ADDH() do { \
        vO0+=hO0; vO1+=hO1; vO2+=hO2; vO3+=hO3; \
        vT0+=hT0; vT1+=hT1; vT2+=hT2; vT3+=hT3; \
        vQ0+=hQ0; vQ1+=hQ1; vQ2+=hQ2; vQ3+=hQ3; \
        vR0+=hR0; vR1+=hR1; vR2+=hR2; vR3+=hR3; \
    } while (0)

#define STORE_RING(S) do { \
        rO0[S]=hO0; rO1[S]=hO1; rO2[S]=hO2; rO3[S]=hO3; \
        rT0[S]=hT0; rT1[S]=hT1; rT2[S]=hT2; rT3[S]=hT3; \
        rQ0[S]=hQ0; rQ1[S]=hQ1; rQ2[S]=hQ2; rQ3[S]=hQ3; \
        rR0[S]=hR0; rR1[S]=hR1; rR2[S]=hR2; rR3[S]=hR3; \
    } while (0)

    // Prime with input rows r0 .. r0+5 (ring slots 0..5).
    {
        ROWH(); ADDH(); STORE_RING(0);
    }
    { ROWH(); ADDH(); STORE_RING(1); }
    { ROWH(); ADDH(); STORE_RING(2); }
    { ROWH(); ADDH(); STORE_RING(3); }
    { ROWH(); ADDH(); STORE_RING(4); }
    { ROWH(); ADDH(); STORE_RING(5); }
    rO0[6]=0.f; rO1[6]=0.f; rO2[6]=0.f; rO3[6]=0.f;
    rT0[6]=0.f; rT1[6]=0.f; rT2[6]=0.f; rT3[6]=0.f;
    rQ0[6]=0.f; rQ1[6]=0.f; rQ2[6]=0.f; rQ3[6]=0.f;
    rR0[6]=0.f; rR1[6]=0.f; rR2[6]=0.f; rR3[6]=0.f;

#define BODY(K) do { \
        ROWH(); ADDH(); \
        SSIM1(vO0, vT0, vQ0, vR0, a0); \
        SSIM1(vO1, vT1, vQ1, vR1, a1); \
        SSIM1(vO2, vT2, vQ2, vR2, a2c); \
        SSIM1(vO3, vT3, vQ3, vR3, a3); \
        vO0-=rO0[K]; vO1-=rO1[K]; vO2-=rO2[K]; vO3-=rO3[K]; \
        vT0-=rT0[K]; vT1-=rT1[K]; vT2-=rT2[K]; vT3-=rT3[K]; \
        vQ0-=rQ0[K]; vQ1-=rQ1[K]; vQ2-=rQ2[K]; vQ3-=rQ3[K]; \
        vR0-=rR0[K]; vR1-=rR1[K]; vR2-=rR2[K]; vR3-=rR3[K]; \
        STORE_RING(((K)+6)%7); \
    } while (0)

    const int full = (rows_out / 7) * 7;
    int j = 0;
    while (j < full) {
        BODY(0); BODY(1); BODY(2); BODY(3); BODY(4); BODY(5); BODY(6);
        j += 7;
    }
    const int rem = rows_out - full;   // 0..6
    if (rem > 0) BODY(0);
    if (rem > 1) BODY(1);
    if (rem > 2) BODY(2);
    if (rem > 3) BODY(3);
    if (rem > 4) BODY(4);
    if (rem > 5) BODY(5);

#undef BODY
#undef STORE_RING
#undef ADDH
#undef SSIM1
#undef ROWH

    // Per-column validity masking (handles partial and fully-clamped threads).
    float acc = 0.f;
    if (ocol + 0 < OWD) acc += a0;
    if (ocol + 1 < OWD) acc += a1;
    if (ocol + 2 < OWD) acc += a2c;
    if (ocol + 3 < OWD) acc += a3;

    #pragma unroll
    for (int off = 16; off; off >>= 1)
        acc += __shfl_xor_sync(0xffffffffu, acc, off);

    __shared__ float ws[TPB / 32];
    const int lane = threadIdx.x & 31;
    const int warp = threadIdx.x >> 5;
    if (lane == 0) ws[warp] = acc;
    __syncthreads();
    if (threadIdx.x == 0) {
        float b = ws[0] + ws[1] + ws[2] + ws[3];
        atomicAdd(&g_sum, (double)b);
        __threadfence();
        unsigned n = atomicAdd(&g_cnt, 1u);
        if (n == NBLK - 1) {
            double s = atomicAdd(&g_sum, 0.0);  // coherent read of final sum
            out[0] = (float)(s * (1.0 / ((double)OWD * (double)OHT)));
            g_sum = 0.0;      // reset for next graph replay (determinism)
            g_cnt = 0u;
        }
    }
}

extern "C" void kernel_launch(void* const* d_in, const int* in_sizes, int n_in,
                              void* d_out, int out_size) {
    const float* O = (const float*)d_in[0];
    const float* T = (const float*)d_in[1];
    ssim_main<<<dim3(GX, NSTR), TPB>>>(O, T, (float*)d_out);
}